// round 10
// baseline (speedup 1.0000x reference)
#include <cuda_runtime.h>

#define N_NODES 100000
#define N_EDGES 1600000
#define NB_SCAN 98            // ceil(100000/1024)
// layer dims: F_IN=128, HID=64, N_CLS=40

// Scratch (device globals: allocation-free, graph-safe)
__device__ __align__(16) float g_y1[N_NODES * 128];   // [x@W1_l | x@W1_r]
__device__ __align__(16) float g_y2[N_NODES * 80];    // [h@W2_l | h@W2_r]
__device__ int g_deg[N_NODES];        // in-degree histogram
__device__ int g_excl[N_NODES];       // block-local exclusive scan
__device__ int g_bsum[NB_SCAN];       // per-block sums
__device__ int g_boff[NB_SCAN];       // scanned block offsets
__device__ int g_ptr[N_NODES + 1];    // CSR row pointers (by dst)
__device__ int g_pos[N_NODES];        // scatter cursors
__device__ int g_csr[N_EDGES];        // src ids grouped by dst

// ---------------------------------------------------------------- f32x2 helpers
__device__ __forceinline__ unsigned long long pk2(float lo, float hi) {
    unsigned long long r;
    asm("mov.b64 %0, {%1, %2};" : "=l"(r) : "f"(lo), "f"(hi));
    return r;
}
__device__ __forceinline__ void fma2(unsigned long long& d,
                                     unsigned long long a, unsigned long long b) {
    asm("fma.rn.f32x2 %0, %1, %2, %0;" : "+l"(d) : "l"(a), "l"(b));
}
__device__ __forceinline__ float sum2(unsigned long long v) {
    float lo, hi;
    asm("mov.b64 {%0, %1}, %2;" : "=f"(lo), "=f"(hi) : "l"(v));
    return lo + hi;
}

// ---------------------------------------------------------------- CSR build
__global__ void zero_deg_kernel() {
    int i = blockIdx.x * blockDim.x + threadIdx.x;
    if (i < N_NODES) g_deg[i] = 0;
}

__global__ void hist_kernel(const int* __restrict__ ei) {
    int e = blockIdx.x * blockDim.x + threadIdx.x;
    if (e >= N_EDGES) return;
    atomicAdd(&g_deg[__ldg(ei + N_EDGES + e)], 1);
}

// warp-shuffle block scan (1024 threads): local exclusive + block sum
__global__ void scan_block_kernel() {
    __shared__ int wsum[32];
    int t = threadIdx.x;
    int i = blockIdx.x * 1024 + t;
    int v = (i < N_NODES) ? g_deg[i] : 0;
    int lane = t & 31, w = t >> 5;

    int incl = v;
    #pragma unroll
    for (int o = 1; o < 32; o <<= 1) {
        int u = __shfl_up_sync(0xFFFFFFFFu, incl, o);
        if (lane >= o) incl += u;
    }
    if (lane == 31) wsum[w] = incl;
    __syncthreads();
    if (w == 0) {
        int s = wsum[lane];
        #pragma unroll
        for (int o = 1; o < 32; o <<= 1) {
            int u = __shfl_up_sync(0xFFFFFFFFu, s, o);
            if (lane >= o) s += u;
        }
        wsum[lane] = s;
    }
    __syncthreads();
    int off = (w > 0) ? wsum[w - 1] : 0;
    incl += off;
    if (i < N_NODES) g_excl[i] = incl - v;
    if (t == 1023) g_bsum[blockIdx.x] = incl;
}

// warp-shuffle scan of the 98 block sums (1 block, 128 threads)
__global__ void scan_bsum_kernel() {
    __shared__ int wsum[4];
    int t = threadIdx.x;
    int v = (t < NB_SCAN) ? g_bsum[t] : 0;
    int lane = t & 31, w = t >> 5;

    int incl = v;
    #pragma unroll
    for (int o = 1; o < 32; o <<= 1) {
        int u = __shfl_up_sync(0xFFFFFFFFu, incl, o);
        if (lane >= o) incl += u;
    }
    if (lane == 31) wsum[w] = incl;
    __syncthreads();
    if (t == 0) {
        int a = wsum[0];
        wsum[1] += a; a = wsum[1];
        wsum[2] += a; a = wsum[2];
        wsum[3] += a;
    }
    __syncthreads();
    int off = (w > 0) ? wsum[w - 1] : 0;
    incl += off;
    if (t < NB_SCAN) g_boff[t] = incl - v;
    if (t == 127) g_ptr[N_NODES] = incl;   // == N_EDGES
}

__global__ void finalize_ptr_kernel() {
    int i = blockIdx.x * blockDim.x + threadIdx.x;
    if (i >= N_NODES) return;
    int p = g_excl[i] + g_boff[i >> 10];
    g_ptr[i] = p;
    g_pos[i] = p;
}

__global__ void scatter_kernel(const int* __restrict__ ei) {
    int e = blockIdx.x * blockDim.x + threadIdx.x;
    if (e >= N_EDGES) return;
    int s = __ldg(ei + e);
    int d = __ldg(ei + N_EDGES + e);
    int p = atomicAdd(&g_pos[d], 1);
    g_csr[p] = s;
}

// ---------------------------------------------------------------- GEMM1 (FFMA2, K-paired)
__global__ void gemm1_kernel(const float* __restrict__ x,
                             const float* __restrict__ Wl,
                             const float* __restrict__ Wr) {
    __shared__ float As[64][128];  // 32 KB
    const int bm = blockIdx.x * 64;
    const int t  = threadIdx.x;

    for (int i = t; i < 64 * 32; i += 256) {
        int m = i >> 5, k4 = i & 31;
        int gm = bm + m;
        float4 v = make_float4(0.f, 0.f, 0.f, 0.f);
        if (gm < N_NODES) v = __ldg((const float4*)x + gm * 32 + k4);
        *(float4*)&As[m][k4 * 4] = v;
    }
    __syncthreads();

    const int ng = t & 31, mg = t >> 5;
    const int n0 = ng * 4, m0 = mg * 8;
    const float* B = (n0 < 64) ? (Wl + n0) : (Wr + (n0 - 64));

    unsigned long long acc[8][4];
    #pragma unroll
    for (int i = 0; i < 8; i++)
        { acc[i][0] = 0ull; acc[i][1] = 0ull; acc[i][2] = 0ull; acc[i][3] = 0ull; }

    #pragma unroll 4
    for (int k = 0; k < 128; k += 2) {
        float4 b0 = __ldg((const float4*)(B + k * 64));
        float4 b1 = __ldg((const float4*)(B + (k + 1) * 64));
        unsigned long long bx = pk2(b0.x, b1.x);
        unsigned long long by = pk2(b0.y, b1.y);
        unsigned long long bz = pk2(b0.z, b1.z);
        unsigned long long bw = pk2(b0.w, b1.w);
        #pragma unroll
        for (int i = 0; i < 8; i++) {
            float2 a = *(const float2*)&As[m0 + i][k];
            unsigned long long ap = pk2(a.x, a.y);
            fma2(acc[i][0], ap, bx);
            fma2(acc[i][1], ap, by);
            fma2(acc[i][2], ap, bz);
            fma2(acc[i][3], ap, bw);
        }
    }

    #pragma unroll
    for (int i = 0; i < 8; i++) {
        int gm = bm + m0 + i;
        if (gm < N_NODES)
            *(float4*)&g_y1[gm * 128 + n0] =
                make_float4(sum2(acc[i][0]), sum2(acc[i][1]),
                            sum2(acc[i][2]), sum2(acc[i][3]));
    }
}

// ---------------------------------------------------------------- FUSED agg1 + gemm2
// Block = 64 nodes, 256 threads.
// Phase A: 4 threads/node aggregate neighbors (each thread owns 16 consecutive
//          floats = 4 float4 chunks of the 64-f l-part), fuse mean+self+bias+relu,
//          stage h into smem.
// Phase B: 160 threads run the 64x80x64 GEMM (FFMA2, K-paired) from smem.
__global__ void fused_agg1_gemm2_kernel(const float* __restrict__ b1,
                                        const float* __restrict__ Wl,
                                        const float* __restrict__ Wr) {
    __shared__ float Hs[64][64];  // 16 KB
    const int bm = blockIdx.x * 64;
    const int t  = threadIdx.x;

    // ---- Phase A: aggregation ----
    {
        int nm = t >> 2;          // node within block (0..63)
        int jc = t & 3;           // chunk group (owns f4 chunks jc*4 .. jc*4+3)
        int gm = bm + nm;
        if (gm < N_NODES) {
            int beg = __ldg(&g_ptr[gm]), end = __ldg(&g_ptr[gm + 1]);
            float4 a0 = make_float4(0.f, 0.f, 0.f, 0.f);
            float4 a1 = a0, a2 = a0, a3 = a0;
            int base_c = jc * 4;

            int k = beg;
            for (; k + 2 <= end; k += 2) {   // 2-edge unroll -> 8 loads in flight
                int s0 = __ldg(&g_csr[k]);
                int s1 = __ldg(&g_csr[k + 1]);
                const float4* r0 = (const float4*)g_y1 + s0 * 32 + base_c;
                const float4* r1 = (const float4*)g_y1 + s1 * 32 + base_c;
                float4 u0 = __ldg(r0 + 0), u1 = __ldg(r0 + 1);
                float4 u2 = __ldg(r0 + 2), u3 = __ldg(r0 + 3);
                float4 w0 = __ldg(r1 + 0), w1 = __ldg(r1 + 1);
                float4 w2 = __ldg(r1 + 2), w3 = __ldg(r1 + 3);
                a0.x += u0.x + w0.x; a0.y += u0.y + w0.y; a0.z += u0.z + w0.z; a0.w += u0.w + w0.w;
                a1.x += u1.x + w1.x; a1.y += u1.y + w1.y; a1.z += u1.z + w1.z; a1.w += u1.w + w1.w;
                a2.x += u2.x + w2.x; a2.y += u2.y + w2.y; a2.z += u2.z + w2.z; a2.w += u2.w + w2.w;
                a3.x += u3.x + w3.x; a3.y += u3.y + w3.y; a3.z += u3.z + w3.z; a3.w += u3.w + w3.w;
            }
            for (; k < end; k++) {
                int s = __ldg(&g_csr[k]);
                const float4* r = (const float4*)g_y1 + s * 32 + base_c;
                float4 u0 = __ldg(r + 0), u1 = __ldg(r + 1);
                float4 u2 = __ldg(r + 2), u3 = __ldg(r + 3);
                a0.x += u0.x; a0.y += u0.y; a0.z += u0.z; a0.w += u0.w;
                a1.x += u1.x; a1.y += u1.y; a1.z += u1.z; a1.w += u1.w;
                a2.x += u2.x; a2.y += u2.y; a2.z += u2.z; a2.w += u2.w;
                a3.x += u3.x; a3.y += u3.y; a3.z += u3.z; a3.w += u3.w;
            }

            float inv = 1.0f / fmaxf((float)(end - beg), 1.0f);
            const float4* selfp = (const float4*)g_y1 + gm * 32 + 16 + base_c;  // r-part
            const float4* bp    = (const float4*)b1 + base_c;
            float4 accs[4] = {a0, a1, a2, a3};
            #pragma unroll
            for (int q = 0; q < 4; q++) {
                float4 s4 = __ldg(selfp + q);
                float4 bb = __ldg(bp + q);
                float4 h;
                h.x = fmaxf(accs[q].x * inv + s4.x + bb.x, 0.f);
                h.y = fmaxf(accs[q].y * inv + s4.y + bb.y, 0.f);
                h.z = fmaxf(accs[q].z * inv + s4.z + bb.z, 0.f);
                h.w = fmaxf(accs[q].w * inv + s4.w + bb.w, 0.f);
                *(float4*)&Hs[nm][(base_c + q) * 4] = h;
            }
        } else {
            // pad rows with zeros so phase B can run unguarded
            int base_c = jc * 4;
            #pragma unroll
            for (int q = 0; q < 4; q++)
                *(float4*)&Hs[nm][(base_c + q) * 4] = make_float4(0.f, 0.f, 0.f, 0.f);
        }
    }
    __syncthreads();

    // ---- Phase B: GEMM from smem (threads 0..159 active) ----
    if (t < 160) {
        const int ng = t % 20, mg = t / 20;
        const int n0 = ng * 4, m0 = mg * 8;
        const float* B = (n0 < 40) ? (Wl + n0) : (Wr + (n0 - 40));

        unsigned long long acc[8][4];
        #pragma unroll
        for (int i = 0; i < 8; i++)
            { acc[i][0] = 0ull; acc[i][1] = 0ull; acc[i][2] = 0ull; acc[i][3] = 0ull; }

        #pragma unroll 4
        for (int k = 0; k < 64; k += 2) {
            float4 b0 = __ldg((const float4*)(B + k * 40));
            float4 b1v = __ldg((const float4*)(B + (k + 1) * 40));
            unsigned long long bx = pk2(b0.x, b1v.x);
            unsigned long long by = pk2(b0.y, b1v.y);
            unsigned long long bz = pk2(b0.z, b1v.z);
            unsigned long long bw = pk2(b0.w, b1v.w);
            #pragma unroll
            for (int i = 0; i < 8; i++) {
                float2 a = *(const float2*)&Hs[m0 + i][k];
                unsigned long long ap = pk2(a.x, a.y);
                fma2(acc[i][0], ap, bx);
                fma2(acc[i][1], ap, by);
                fma2(acc[i][2], ap, bz);
                fma2(acc[i][3], ap, bw);
            }
        }

        #pragma unroll
        for (int i = 0; i < 8; i++) {
            int gm = bm + m0 + i;
            if (gm < N_NODES)
                *(float4*)&g_y2[gm * 80 + n0] =
                    make_float4(sum2(acc[i][0]), sum2(acc[i][1]),
                                sum2(acc[i][2]), sum2(acc[i][3]));
        }
    }
}

// ---------------------------------------------------------------- agg2 + log_softmax (fused)
// 2 nodes per warp (16-lane halves); sublanes 0..9 own the 10 float4 chunks
// of the 40-f z-part. Reductions via width-16 shuffles.
__global__ void agg2_kernel(const float* __restrict__ b2, float* __restrict__ out) {
    int gw   = (blockIdx.x * blockDim.x + threadIdx.x) >> 5;   // warp id
    int lane = threadIdx.x & 31;
    int half = lane >> 4;          // which node in the pair
    int sl   = lane & 15;          // sublane within the 16-lane group
    int n = gw * 2 + half;
    if (n >= N_NODES) return;

    int beg = __ldg(&g_ptr[n]), end = __ldg(&g_ptr[n + 1]);
    bool act = sl < 10;
    float4 acc = make_float4(0.f, 0.f, 0.f, 0.f);

    int k = beg;
    for (; k + 4 <= end; k += 4) {
        int s0 = __ldg(&g_csr[k]);
        int s1 = __ldg(&g_csr[k + 1]);
        int s2 = __ldg(&g_csr[k + 2]);
        int s3 = __ldg(&g_csr[k + 3]);
        if (act) {
            float4 v0 = __ldg((const float4*)g_y2 + s0 * 20 + sl);
            float4 v1 = __ldg((const float4*)g_y2 + s1 * 20 + sl);
            float4 v2 = __ldg((const float4*)g_y2 + s2 * 20 + sl);
            float4 v3 = __ldg((const float4*)g_y2 + s3 * 20 + sl);
            acc.x += v0.x + v1.x + v2.x + v3.x;
            acc.y += v0.y + v1.y + v2.y + v3.y;
            acc.z += v0.z + v1.z + v2.z + v3.z;
            acc.w += v0.w + v1.w + v2.w + v3.w;
        }
    }
    for (; k < end; k++) {
        int s = __ldg(&g_csr[k]);
        if (act) {
            float4 v = __ldg((const float4*)g_y2 + s * 20 + sl);
            acc.x += v.x; acc.y += v.y; acc.z += v.z; acc.w += v.w;
        }
    }

    float inv = 1.0f / fmaxf((float)(end - beg), 1.0f);
    float4 v = make_float4(-3.0e38f, -3.0e38f, -3.0e38f, -3.0e38f);
    if (act) {
        float4 self = __ldg((const float4*)g_y2 + n * 20 + 10 + sl);  // r-part
        float4 bb   = __ldg((const float4*)b2 + sl);
        v.x = acc.x * inv + self.x + bb.x;
        v.y = acc.y * inv + self.y + bb.y;
        v.z = acc.z * inv + self.z + bb.z;
        v.w = acc.w * inv + self.w + bb.w;
    }

    float m = fmaxf(fmaxf(v.x, v.y), fmaxf(v.z, v.w));
    #pragma unroll
    for (int o = 8; o; o >>= 1) m = fmaxf(m, __shfl_xor_sync(0xFFFFFFFFu, m, o, 16));

    float s = act ? (expf(v.x - m) + expf(v.y - m) + expf(v.z - m) + expf(v.w - m)) : 0.f;
    #pragma unroll
    for (int o = 8; o; o >>= 1) s += __shfl_xor_sync(0xFFFFFFFFu, s, o, 16);

    float lse = m + logf(s);
    if (act)
        *((float4*)out + n * 10 + sl) =
            make_float4(v.x - lse, v.y - lse, v.z - lse, v.w - lse);
}

// ---------------------------------------------------------------- launch
// Captured graph: main stream runs gemm1 concurrently with the CSR chain on a
// side stream; join; fused agg1+gemm2; agg2.
extern "C" void kernel_launch(void* const* d_in, const int* in_sizes, int n_in,
                              void* d_out, int out_size) {
    const float* x   = 0; const int* ei = 0;
    const float* W1l = 0; const float* W1r = 0; const float* b1 = 0;
    const float* W2l = 0; const float* W2r = 0; const float* b2 = 0;

    for (int i = 0; i < n_in; i++) {
        int sz = in_sizes[i];
        const void* p = d_in[i];
        if      (sz == N_NODES * 128)  x  = (const float*)p;
        else if (sz == 2 * N_EDGES)    ei = (const int*)p;
        else if (sz == 128 * 64) { if (!W1l) W1l = (const float*)p; else W1r = (const float*)p; }
        else if (sz == 64 * 40)  { if (!W2l) W2l = (const float*)p; else W2r = (const float*)p; }
        else if (sz == 64)             b1 = (const float*)p;
        else if (sz == 40)             b2 = (const float*)p;
    }
    float* out = (float*)d_out;

    cudaStream_t s1;
    cudaEvent_t evFork, evJoin;
    cudaStreamCreateWithFlags(&s1, cudaStreamNonBlocking);
    cudaEventCreateWithFlags(&evFork, cudaEventDisableTiming);
    cudaEventCreateWithFlags(&evJoin, cudaEventDisableTiming);

    cudaEventRecord(evFork, 0);
    cudaStreamWaitEvent(s1, evFork, 0);

    // side stream: CSR build
    zero_deg_kernel    <<<(N_NODES + 255) / 256, 256, 0, s1>>>();
    hist_kernel        <<<(N_EDGES + 255) / 256, 256, 0, s1>>>(ei);
    scan_block_kernel  <<<NB_SCAN, 1024, 0, s1>>>();
    scan_bsum_kernel   <<<1, 128, 0, s1>>>();
    finalize_ptr_kernel<<<(N_NODES + 255) / 256, 256, 0, s1>>>();
    scatter_kernel     <<<(N_EDGES + 255) / 256, 256, 0, s1>>>(ei);
    cudaEventRecord(evJoin, s1);

    // main stream: gemm1 runs concurrently with the CSR chain
    gemm1_kernel<<<(N_NODES + 63) / 64, 256>>>(x, W1l, W1r);

    // join, then the dependent tail
    cudaStreamWaitEvent(0, evJoin, 0);
    fused_agg1_gemm2_kernel<<<(N_NODES + 63) / 64, 256>>>(b1, W2l, W2r);
    agg2_kernel<<<(N_NODES / 2 * 32 + 255) / 256, 256>>>(b2, out);
}

// round 11
// speedup vs baseline: 1.1435x; 1.1435x over previous
#include <cuda_runtime.h>

#define N_NODES 100000
#define N_EDGES 1600000
#define NB_SCAN 98            // ceil(100000/1024)
// layer dims: F_IN=128, HID=64, N_CLS=40

// Scratch (device globals: allocation-free, graph-safe)
__device__ __align__(16) float g_y1[N_NODES * 128];   // [x@W1_l | x@W1_r]
__device__ __align__(16) float g_h[N_NODES * 64];     // relu output
__device__ __align__(16) float g_y2[N_NODES * 80];    // [h@W2_l | h@W2_r]
__device__ int g_deg[N_NODES];        // in-degree histogram
__device__ int g_excl[N_NODES];       // block-local exclusive scan
__device__ int g_bsum[NB_SCAN];       // per-block sums
__device__ int g_boff[NB_SCAN];       // scanned block offsets
__device__ int g_ptr[N_NODES + 1];    // CSR row pointers (by dst)
__device__ int g_pos[N_NODES];        // scatter cursors
__device__ int g_csr[N_EDGES];        // src ids grouped by dst

// ---------------------------------------------------------------- f32x2 helpers
__device__ __forceinline__ unsigned long long pk2(float lo, float hi) {
    unsigned long long r;
    asm("mov.b64 %0, {%1, %2};" : "=l"(r) : "f"(lo), "f"(hi));
    return r;
}
__device__ __forceinline__ void fma2(unsigned long long& d,
                                     unsigned long long a, unsigned long long b) {
    asm("fma.rn.f32x2 %0, %1, %2, %0;" : "+l"(d) : "l"(a), "l"(b));
}
__device__ __forceinline__ float sum2(unsigned long long v) {
    float lo, hi;
    asm("mov.b64 {%0, %1}, %2;" : "=f"(lo), "=f"(hi) : "l"(v));
    return lo + hi;
}

// ---------------------------------------------------------------- CSR build
__global__ void zero_deg_kernel() {
    int i = blockIdx.x * blockDim.x + threadIdx.x;
    if (i < N_NODES) g_deg[i] = 0;
}

__global__ void hist_kernel(const int* __restrict__ ei) {
    int e = blockIdx.x * blockDim.x + threadIdx.x;
    if (e >= N_EDGES) return;
    atomicAdd(&g_deg[__ldg(ei + N_EDGES + e)], 1);
}

// warp-shuffle block scan (1024 threads): local exclusive + block sum
__global__ void scan_block_kernel() {
    __shared__ int wsum[32];
    int t = threadIdx.x;
    int i = blockIdx.x * 1024 + t;
    int v = (i < N_NODES) ? g_deg[i] : 0;
    int lane = t & 31, w = t >> 5;

    int incl = v;
    #pragma unroll
    for (int o = 1; o < 32; o <<= 1) {
        int u = __shfl_up_sync(0xFFFFFFFFu, incl, o);
        if (lane >= o) incl += u;
    }
    if (lane == 31) wsum[w] = incl;
    __syncthreads();
    if (w == 0) {
        int s = wsum[lane];
        #pragma unroll
        for (int o = 1; o < 32; o <<= 1) {
            int u = __shfl_up_sync(0xFFFFFFFFu, s, o);
            if (lane >= o) s += u;
        }
        wsum[lane] = s;
    }
    __syncthreads();
    int off = (w > 0) ? wsum[w - 1] : 0;
    incl += off;
    if (i < N_NODES) g_excl[i] = incl - v;
    if (t == 1023) g_bsum[blockIdx.x] = incl;
}

// warp-shuffle scan of the 98 block sums (1 block, 128 threads)
__global__ void scan_bsum_kernel() {
    __shared__ int wsum[4];
    int t = threadIdx.x;
    int v = (t < NB_SCAN) ? g_bsum[t] : 0;
    int lane = t & 31, w = t >> 5;

    int incl = v;
    #pragma unroll
    for (int o = 1; o < 32; o <<= 1) {
        int u = __shfl_up_sync(0xFFFFFFFFu, incl, o);
        if (lane >= o) incl += u;
    }
    if (lane == 31) wsum[w] = incl;
    __syncthreads();
    if (t == 0) {
        int a = wsum[0];
        wsum[1] += a; a = wsum[1];
        wsum[2] += a; a = wsum[2];
        wsum[3] += a;
    }
    __syncthreads();
    int off = (w > 0) ? wsum[w - 1] : 0;
    incl += off;
    if (t < NB_SCAN) g_boff[t] = incl - v;
    if (t == 127) g_ptr[N_NODES] = incl;   // == N_EDGES
}

__global__ void finalize_ptr_kernel() {
    int i = blockIdx.x * blockDim.x + threadIdx.x;
    if (i >= N_NODES) return;
    int p = g_excl[i] + g_boff[i >> 10];
    g_ptr[i] = p;
    g_pos[i] = p;
}

__global__ void scatter_kernel(const int* __restrict__ ei) {
    int e = blockIdx.x * blockDim.x + threadIdx.x;
    if (e >= N_EDGES) return;
    int s = __ldg(ei + e);
    int d = __ldg(ei + N_EDGES + e);
    int p = atomicAdd(&g_pos[d], 1);
    g_csr[p] = s;
}

// ---------------------------------------------------------------- GEMM1 (FFMA2, K-paired)
__global__ void gemm1_kernel(const float* __restrict__ x,
                             const float* __restrict__ Wl,
                             const float* __restrict__ Wr) {
    __shared__ float As[64][128];  // 32 KB
    const int bm = blockIdx.x * 64;
    const int t  = threadIdx.x;

    for (int i = t; i < 64 * 32; i += 256) {
        int m = i >> 5, k4 = i & 31;
        int gm = bm + m;
        float4 v = make_float4(0.f, 0.f, 0.f, 0.f);
        if (gm < N_NODES) v = __ldg((const float4*)x + gm * 32 + k4);
        *(float4*)&As[m][k4 * 4] = v;
    }
    __syncthreads();

    const int ng = t & 31, mg = t >> 5;
    const int n0 = ng * 4, m0 = mg * 8;
    const float* B = (n0 < 64) ? (Wl + n0) : (Wr + (n0 - 64));

    unsigned long long acc[8][4];
    #pragma unroll
    for (int i = 0; i < 8; i++)
        { acc[i][0] = 0ull; acc[i][1] = 0ull; acc[i][2] = 0ull; acc[i][3] = 0ull; }

    #pragma unroll 4
    for (int k = 0; k < 128; k += 2) {
        float4 b0 = __ldg((const float4*)(B + k * 64));
        float4 b1 = __ldg((const float4*)(B + (k + 1) * 64));
        unsigned long long bx = pk2(b0.x, b1.x);
        unsigned long long by = pk2(b0.y, b1.y);
        unsigned long long bz = pk2(b0.z, b1.z);
        unsigned long long bw = pk2(b0.w, b1.w);
        #pragma unroll
        for (int i = 0; i < 8; i++) {
            float2 a = *(const float2*)&As[m0 + i][k];
            unsigned long long ap = pk2(a.x, a.y);
            fma2(acc[i][0], ap, bx);
            fma2(acc[i][1], ap, by);
            fma2(acc[i][2], ap, bz);
            fma2(acc[i][3], ap, bw);
        }
    }

    #pragma unroll
    for (int i = 0; i < 8; i++) {
        int gm = bm + m0 + i;
        if (gm < N_NODES)
            *(float4*)&g_y1[gm * 128 + n0] =
                make_float4(sum2(acc[i][0]), sum2(acc[i][1]),
                            sum2(acc[i][2]), sum2(acc[i][3]));
    }
}

// ---------------------------------------------------------------- agg1 (fused mean-agg + self + bias + relu)
// 16 threads per node (2 nodes/warp); thread j owns float4 chunk j of the
// 64-f l-part.
__global__ void agg1_kernel(const float* __restrict__ b1) {
    int g = (blockIdx.x * blockDim.x + threadIdx.x) >> 4;
    int j = threadIdx.x & 15;
    if (g >= N_NODES) return;

    int beg = __ldg(&g_ptr[g]), end = __ldg(&g_ptr[g + 1]);
    float4 acc = make_float4(0.f, 0.f, 0.f, 0.f);

    int k = beg;
    for (; k + 4 <= end; k += 4) {
        int s0 = __ldg(&g_csr[k]);
        int s1 = __ldg(&g_csr[k + 1]);
        int s2 = __ldg(&g_csr[k + 2]);
        int s3 = __ldg(&g_csr[k + 3]);
        float4 v0 = __ldg((const float4*)g_y1 + s0 * 32 + j);
        float4 v1 = __ldg((const float4*)g_y1 + s1 * 32 + j);
        float4 v2 = __ldg((const float4*)g_y1 + s2 * 32 + j);
        float4 v3 = __ldg((const float4*)g_y1 + s3 * 32 + j);
        acc.x += v0.x + v1.x + v2.x + v3.x;
        acc.y += v0.y + v1.y + v2.y + v3.y;
        acc.z += v0.z + v1.z + v2.z + v3.z;
        acc.w += v0.w + v1.w + v2.w + v3.w;
    }
    for (; k < end; k++) {
        int s = __ldg(&g_csr[k]);
        float4 v = __ldg((const float4*)g_y1 + s * 32 + j);
        acc.x += v.x; acc.y += v.y; acc.z += v.z; acc.w += v.w;
    }

    float inv = 1.0f / fmaxf((float)(end - beg), 1.0f);
    float4 self = __ldg((const float4*)g_y1 + g * 32 + 16 + j);
    float4 bb   = __ldg((const float4*)b1 + j);
    float4 h;
    h.x = fmaxf(acc.x * inv + self.x + bb.x, 0.f);
    h.y = fmaxf(acc.y * inv + self.y + bb.y, 0.f);
    h.z = fmaxf(acc.z * inv + self.z + bb.z, 0.f);
    h.w = fmaxf(acc.w * inv + self.w + bb.w, 0.f);
    *((float4*)g_h + g * 16 + j) = h;
}

// ---------------------------------------------------------------- GEMM2 (FFMA2, K-paired)
__global__ void gemm2_kernel(const float* __restrict__ Wl,
                             const float* __restrict__ Wr) {
    __shared__ float As[64][64];  // 16 KB
    const int bm = blockIdx.x * 64;
    const int t  = threadIdx.x;

    for (int i = t; i < 64 * 16; i += 160) {
        int m = i >> 4, k4 = i & 15;
        int gm = bm + m;
        float4 v = make_float4(0.f, 0.f, 0.f, 0.f);
        if (gm < N_NODES) v = *((const float4*)g_h + gm * 16 + k4);
        *(float4*)&As[m][k4 * 4] = v;
    }
    __syncthreads();

    const int ng = t % 20, mg = t / 20;
    const int n0 = ng * 4, m0 = mg * 8;
    const float* B = (n0 < 40) ? (Wl + n0) : (Wr + (n0 - 40));

    unsigned long long acc[8][4];
    #pragma unroll
    for (int i = 0; i < 8; i++)
        { acc[i][0] = 0ull; acc[i][1] = 0ull; acc[i][2] = 0ull; acc[i][3] = 0ull; }

    #pragma unroll 4
    for (int k = 0; k < 64; k += 2) {
        float4 b0 = __ldg((const float4*)(B + k * 40));
        float4 b1 = __ldg((const float4*)(B + (k + 1) * 40));
        unsigned long long bx = pk2(b0.x, b1.x);
        unsigned long long by = pk2(b0.y, b1.y);
        unsigned long long bz = pk2(b0.z, b1.z);
        unsigned long long bw = pk2(b0.w, b1.w);
        #pragma unroll
        for (int i = 0; i < 8; i++) {
            float2 a = *(const float2*)&As[m0 + i][k];
            unsigned long long ap = pk2(a.x, a.y);
            fma2(acc[i][0], ap, bx);
            fma2(acc[i][1], ap, by);
            fma2(acc[i][2], ap, bz);
            fma2(acc[i][3], ap, bw);
        }
    }

    #pragma unroll
    for (int i = 0; i < 8; i++) {
        int gm = bm + m0 + i;
        if (gm < N_NODES)
            *(float4*)&g_y2[gm * 80 + n0] =
                make_float4(sum2(acc[i][0]), sum2(acc[i][1]),
                            sum2(acc[i][2]), sum2(acc[i][3]));
    }
}

// ---------------------------------------------------------------- agg2 + log_softmax (fused)
// 2 nodes per warp (16-lane halves); sublanes 0..9 own the 10 float4 chunks
// of the 40-f z-part. Reductions via width-16 shuffles.
__global__ void agg2_kernel(const float* __restrict__ b2, float* __restrict__ out) {
    int gw   = (blockIdx.x * blockDim.x + threadIdx.x) >> 5;   // warp id
    int lane = threadIdx.x & 31;
    int half = lane >> 4;          // which node in the pair
    int sl   = lane & 15;          // sublane within the 16-lane group
    int n = gw * 2 + half;
    if (n >= N_NODES) return;

    int beg = __ldg(&g_ptr[n]), end = __ldg(&g_ptr[n + 1]);
    bool act = sl < 10;
    float4 acc = make_float4(0.f, 0.f, 0.f, 0.f);

    int k = beg;
    for (; k + 4 <= end; k += 4) {
        int s0 = __ldg(&g_csr[k]);
        int s1 = __ldg(&g_csr[k + 1]);
        int s2 = __ldg(&g_csr[k + 2]);
        int s3 = __ldg(&g_csr[k + 3]);
        if (act) {
            float4 v0 = __ldg((const float4*)g_y2 + s0 * 20 + sl);
            float4 v1 = __ldg((const float4*)g_y2 + s1 * 20 + sl);
            float4 v2 = __ldg((const float4*)g_y2 + s2 * 20 + sl);
            float4 v3 = __ldg((const float4*)g_y2 + s3 * 20 + sl);
            acc.x += v0.x + v1.x + v2.x + v3.x;
            acc.y += v0.y + v1.y + v2.y + v3.y;
            acc.z += v0.z + v1.z + v2.z + v3.z;
            acc.w += v0.w + v1.w + v2.w + v3.w;
        }
    }
    for (; k < end; k++) {
        int s = __ldg(&g_csr[k]);
        if (act) {
            float4 v = __ldg((const float4*)g_y2 + s * 20 + sl);
            acc.x += v.x; acc.y += v.y; acc.z += v.z; acc.w += v.w;
        }
    }

    float inv = 1.0f / fmaxf((float)(end - beg), 1.0f);
    float4 v = make_float4(-3.0e38f, -3.0e38f, -3.0e38f, -3.0e38f);
    if (act) {
        float4 self = __ldg((const float4*)g_y2 + n * 20 + 10 + sl);
        float4 bb   = __ldg((const float4*)b2 + sl);
        v.x = acc.x * inv + self.x + bb.x;
        v.y = acc.y * inv + self.y + bb.y;
        v.z = acc.z * inv + self.z + bb.z;
        v.w = acc.w * inv + self.w + bb.w;
    }

    float m = fmaxf(fmaxf(v.x, v.y), fmaxf(v.z, v.w));
    #pragma unroll
    for (int o = 8; o; o >>= 1) m = fmaxf(m, __shfl_xor_sync(0xFFFFFFFFu, m, o, 16));

    float s = act ? (expf(v.x - m) + expf(v.y - m) + expf(v.z - m) + expf(v.w - m)) : 0.f;
    #pragma unroll
    for (int o = 8; o; o >>= 1) s += __shfl_xor_sync(0xFFFFFFFFu, s, o, 16);

    float lse = m + logf(s);
    if (act)
        *((float4*)out + n * 10 + sl) =
            make_float4(v.x - lse, v.y - lse, v.z - lse, v.w - lse);
}

// ---------------------------------------------------------------- launch
// Captured graph: main stream runs gemm1 concurrently with the CSR chain on a
// side stream; join; agg1; gemm2; agg2.
extern "C" void kernel_launch(void* const* d_in, const int* in_sizes, int n_in,
                              void* d_out, int out_size) {
    const float* x   = 0; const int* ei = 0;
    const float* W1l = 0; const float* W1r = 0; const float* b1 = 0;
    const float* W2l = 0; const float* W2r = 0; const float* b2 = 0;

    for (int i = 0; i < n_in; i++) {
        int sz = in_sizes[i];
        const void* p = d_in[i];
        if      (sz == N_NODES * 128)  x  = (const float*)p;
        else if (sz == 2 * N_EDGES)    ei = (const int*)p;
        else if (sz == 128 * 64) { if (!W1l) W1l = (const float*)p; else W1r = (const float*)p; }
        else if (sz == 64 * 40)  { if (!W2l) W2l = (const float*)p; else W2r = (const float*)p; }
        else if (sz == 64)             b1 = (const float*)p;
        else if (sz == 40)             b2 = (const float*)p;
    }
    float* out = (float*)d_out;

    cudaStream_t s1;
    cudaEvent_t evFork, evJoin;
    cudaStreamCreateWithFlags(&s1, cudaStreamNonBlocking);
    cudaEventCreateWithFlags(&evFork, cudaEventDisableTiming);
    cudaEventCreateWithFlags(&evJoin, cudaEventDisableTiming);

    cudaEventRecord(evFork, 0);
    cudaStreamWaitEvent(s1, evFork, 0);

    // side stream: CSR build
    zero_deg_kernel    <<<(N_NODES + 255) / 256, 256, 0, s1>>>();
    hist_kernel        <<<(N_EDGES + 255) / 256, 256, 0, s1>>>(ei);
    scan_block_kernel  <<<NB_SCAN, 1024, 0, s1>>>();
    scan_bsum_kernel   <<<1, 128, 0, s1>>>();
    finalize_ptr_kernel<<<(N_NODES + 255) / 256, 256, 0, s1>>>();
    scatter_kernel     <<<(N_EDGES + 255) / 256, 256, 0, s1>>>(ei);
    cudaEventRecord(evJoin, s1);

    // main stream: gemm1 runs concurrently with the CSR chain
    gemm1_kernel<<<(N_NODES + 63) / 64, 256>>>(x, W1l, W1r);

    // join, then the dependent tail
    cudaStreamWaitEvent(0, evJoin, 0);
    agg1_kernel <<<(N_NODES * 16 + 255) / 256, 256>>>(b1);
    gemm2_kernel<<<(N_NODES + 63) / 64, 160>>>(W2l, W2r);
    agg2_kernel <<<(N_NODES / 2 * 32 + 255) / 256, 256>>>(b2, out);
}